// round 5
// baseline (speedup 1.0000x reference)
#include <cuda_runtime.h>
#include <cstdint>

#define NUM_NODES  100000
#define NUM_EDGES  400000
#define F_IN       16
#define F_EDGE     8
#define EMB        16
#define NUM_GRAPHS 256

// ---------------- scratch (no allocations allowed) ----------------
__device__ __align__(16) float g_sums[NUM_NODES * EMB];   // per-node message sums
__device__ float    g_cnt [NUM_NODES];                    // in-degree
__device__ float    g_gsum[NUM_GRAPHS * EMB];             // per-graph sum of h
__device__ unsigned g_gmax[NUM_GRAPHS * EMB];             // per-graph max of h (h>=0)
__device__ float    g_gcnt[NUM_GRAPHS];                   // nodes per graph

// ---------------- packed f32x2 helpers (Blackwell) ----------------
__device__ __forceinline__ unsigned long long pk2(float lo, float hi) {
    unsigned long long r;
    asm("mov.b64 %0, {%1, %2};" : "=l"(r) : "f"(lo), "f"(hi));
    return r;
}
__device__ __forceinline__ void unpk2(unsigned long long v, float& lo, float& hi) {
    asm("mov.b64 {%0, %1}, %2;" : "=f"(lo), "=f"(hi) : "l"(v));
}
__device__ __forceinline__ unsigned long long fma2(unsigned long long a,
                                                   unsigned long long b,
                                                   unsigned long long c) {
    unsigned long long d;
    asm("fma.rn.f32x2 %0, %1, %2, %3;" : "=l"(d) : "l"(a), "l"(b), "l"(c));
    return d;
}

// ---------------- kernel 0: zero scratch ----------------
__global__ void zero_kernel() {
    int i = blockIdx.x * blockDim.x + threadIdx.x;
    int stride = gridDim.x * blockDim.x;
    float4 z4 = make_float4(0.f, 0.f, 0.f, 0.f);
    float4* s4 = reinterpret_cast<float4*>(g_sums);
    for (int k = i; k < NUM_NODES * EMB / 4; k += stride) s4[k] = z4;
    for (int k = i; k < NUM_NODES;       k += stride) g_cnt[k]  = 0.f;
    for (int k = i; k < NUM_GRAPHS * EMB; k += stride) { g_gsum[k] = 0.f; g_gmax[k] = 0u; }
    for (int k = i; k < NUM_GRAPHS;      k += stride) g_gcnt[k] = 0.f;
}

// ---------------- kernel 1: per-edge MLP + message + scatter ----------------
// 16 threads per edge; thread owns output column o = lane & 15.
// Per-thread register-resident weight slice: W[(i*16+o)*8 + f] for i=0..15, f=0..7.
__global__ __launch_bounds__(128)
void edge_kernel(const float* __restrict__ x,
                 const int*   __restrict__ ei,
                 const float* __restrict__ ea,
                 const float* __restrict__ nn1_w,
                 const float* __restrict__ nn1_b) {
    const int lane = threadIdx.x & 31;
    const int o    = lane & 15;
    const int half = lane >> 4;            // which edge within the warp (0/1)

    // load this thread's weight slice (packed pairs over f) + bias
    unsigned long long w2[16][4];
    float b[16];
    #pragma unroll
    for (int i = 0; i < 16; i++) {
        const ulonglong2* p = reinterpret_cast<const ulonglong2*>(nn1_w + (size_t)(i * 16 + o) * 8);
        ulonglong2 a0 = p[0], a1 = p[1];
        w2[i][0] = a0.x; w2[i][1] = a0.y; w2[i][2] = a1.x; w2[i][3] = a1.y;
        b[i] = nn1_b[i * 16 + o];
    }

    const int group = threadIdx.x >> 4;    // 0..7 within block
    const int gpb   = blockDim.x >> 4;     // 8 edges / block
    int e = blockIdx.x * gpb + group;
    const int estep = gridDim.x * gpb;

    // Within a warp the two groups' start indices differ by 1 (even, odd pair);
    // the residue boundary (400000 mod 8192 = 6784) is even, so both groups
    // always run the same trip count -> full-mask shuffles are safe.
    for (; e < NUM_EDGES; e += estep) {
        const int src = ei[e];
        const int dst = ei[NUM_EDGES + e];

        const ulonglong2* pe = reinterpret_cast<const ulonglong2*>(ea + (size_t)e * 8);
        ulonglong2 e0 = pe[0], e1 = pe[1];
        unsigned long long ev0 = e0.x, ev1 = e0.y, ev2 = e1.x, ev3 = e1.y;

        const float xv = x[(size_t)src * 16 + o];

        float acc = 0.f;
        #pragma unroll
        for (int i = 0; i < 16; i++) {
            unsigned long long t2 = fma2(ev0, w2[i][0], pk2(b[i], 0.f));
            t2 = fma2(ev1, w2[i][1], t2);
            t2 = fma2(ev2, w2[i][2], t2);
            t2 = fma2(ev3, w2[i][3], t2);
            float lo, hi; unpk2(t2, lo, hi);
            const float t = fmaxf(lo + hi, 0.f);           // relu(edge MLP output (i,o))
            const float xi = __shfl_sync(0xffffffffu, xv, (half << 4) + i);
            acc = fmaf(xi, t, acc);
        }

        atomicAdd(&g_sums[(size_t)dst * 16 + o], acc);
        if (o == 0) atomicAdd(&g_cnt[dst], 1.f);
    }
}

// ---------------- kernel 2: node update + per-graph pooling ----------------
__global__ __launch_bounds__(256)
void node_kernel(const float* __restrict__ x,
                 const int*   __restrict__ batch,
                 const float* __restrict__ root_w,
                 const float* __restrict__ conv_b) {
    __shared__ float rw[256];
    __shared__ float cb[16];
    rw[threadIdx.x] = root_w[threadIdx.x];
    if (threadIdx.x < 16) cb[threadIdx.x] = conv_b[threadIdx.x];
    __syncthreads();

    const int n = blockIdx.x * blockDim.x + threadIdx.x;
    if (n >= NUM_NODES) return;   // NUM_NODES % 32 == 0 -> whole warps exit together

    // load x row
    float xr[16];
    {
        const float4* px = reinterpret_cast<const float4*>(x + (size_t)n * 16);
        float4 a = px[0], bq = px[1], c = px[2], d = px[3];
        xr[0]=a.x; xr[1]=a.y; xr[2]=a.z; xr[3]=a.w;
        xr[4]=bq.x; xr[5]=bq.y; xr[6]=bq.z; xr[7]=bq.w;
        xr[8]=c.x; xr[9]=c.y; xr[10]=c.z; xr[11]=c.w;
        xr[12]=d.x; xr[13]=d.y; xr[14]=d.z; xr[15]=d.w;
    }
    // load message sums
    float s[16];
    {
        const float4* ps = reinterpret_cast<const float4*>(g_sums + (size_t)n * 16);
        float4 a = ps[0], bq = ps[1], c = ps[2], d = ps[3];
        s[0]=a.x; s[1]=a.y; s[2]=a.z; s[3]=a.w;
        s[4]=bq.x; s[5]=bq.y; s[6]=bq.z; s[7]=bq.w;
        s[8]=c.x; s[9]=c.y; s[10]=c.z; s[11]=c.w;
        s[12]=d.x; s[13]=d.y; s[14]=d.z; s[15]=d.w;
    }
    const float inv = 1.f / fmaxf(g_cnt[n], 1.f);

    float h[16];
    #pragma unroll
    for (int o = 0; o < 16; o++) {
        float a = fmaf(s[o], inv, cb[o]);
        #pragma unroll
        for (int i = 0; i < 16; i++) a = fmaf(xr[i], rw[o * 16 + i], a);
        h[o] = fmaxf(a, 0.f);
    }

    // per-graph pooling; batch is sorted, so most warps are graph-uniform
    const int g = batch[n];
    const unsigned full = 0xffffffffu;
    const int g0 = __shfl_sync(full, g, 0);
    const bool uni = __all_sync(full, g == g0);
    const int lane = threadIdx.x & 31;

    if (uni) {
        #pragma unroll
        for (int o = 0; o < 16; o++) {
            float sv = h[o], mv = h[o];
            #pragma unroll
            for (int off = 16; off > 0; off >>= 1) {
                sv += __shfl_xor_sync(full, sv, off);
                mv = fmaxf(mv, __shfl_xor_sync(full, mv, off));
            }
            if (lane == 0) {
                atomicAdd(&g_gsum[g0 * 16 + o], sv);
                atomicMax(&g_gmax[g0 * 16 + o], __float_as_uint(mv));
            }
        }
        if (lane == 0) atomicAdd(&g_gcnt[g0], 32.f);
    } else {
        #pragma unroll
        for (int o = 0; o < 16; o++) {
            atomicAdd(&g_gsum[g * 16 + o], h[o]);
            atomicMax(&g_gmax[g * 16 + o], __float_as_uint(h[o]));
        }
        atomicAdd(&g_gcnt[g], 1.f);
    }
}

// ---------------- kernel 3: per-graph head ----------------
__global__ __launch_bounds__(256)
void head_kernel(const float* __restrict__ lin1_w,
                 const float* __restrict__ lin1_b,
                 const float* __restrict__ lin2_w,
                 const float* __restrict__ lin2_b,
                 float* __restrict__ out) {
    __shared__ float w1[16 * 32];
    __shared__ float b1[16];
    __shared__ float w2[16];
    __shared__ float b2;
    for (int i = threadIdx.x; i < 16 * 32; i += blockDim.x) w1[i] = lin1_w[i];
    if (threadIdx.x < 16) { b1[threadIdx.x] = lin1_b[threadIdx.x]; w2[threadIdx.x] = lin2_w[threadIdx.x]; }
    if (threadIdx.x == 0) b2 = lin2_b[0];
    __syncthreads();

    const int g = threadIdx.x;   // 256 graphs, 1 block of 256 threads
    float p[32];
    #pragma unroll
    for (int j = 0; j < 16; j++) p[j] = __uint_as_float(g_gmax[g * 16 + j]);
    const float inv = 1.f / fmaxf(g_gcnt[g], 1.f);
    #pragma unroll
    for (int j = 0; j < 16; j++) p[16 + j] = g_gsum[g * 16 + j] * inv;

    float acc = b2;
    #pragma unroll
    for (int k = 0; k < 16; k++) {
        float a = b1[k];
        #pragma unroll
        for (int j = 0; j < 32; j++) a = fmaf(p[j], w1[k * 32 + j], a);
        acc = fmaf(fmaxf(a, 0.f), w2[k], acc);
    }
    out[g] = acc;
}

// ---------------- launch ----------------
extern "C" void kernel_launch(void* const* d_in, const int* in_sizes, int n_in,
                              void* d_out, int out_size) {
    const float* x      = (const float*)d_in[0];
    const int*   ei     = (const int*)  d_in[1];
    const float* ea     = (const float*)d_in[2];
    const int*   batch  = (const int*)  d_in[3];
    const float* nn1_w  = (const float*)d_in[4];
    const float* nn1_b  = (const float*)d_in[5];
    const float* root_w = (const float*)d_in[6];
    const float* conv_b = (const float*)d_in[7];
    const float* lin1_w = (const float*)d_in[8];
    const float* lin1_b = (const float*)d_in[9];
    const float* lin2_w = (const float*)d_in[10];
    const float* lin2_b = (const float*)d_in[11];
    float* out = (float*)d_out;

    zero_kernel<<<512, 256>>>();
    edge_kernel<<<1024, 128>>>(x, ei, ea, nn1_w, nn1_b);
    node_kernel<<<(NUM_NODES + 255) / 256, 256>>>(x, batch, root_w, conv_b);
    head_kernel<<<1, 256>>>(lin1_w, lin1_b, lin2_w, lin2_b, out);
}

// round 7
// speedup vs baseline: 1.4446x; 1.4446x over previous
#include <cuda_runtime.h>
#include <cstdint>

#define NUM_NODES  100000
#define NUM_EDGES  400000
#define F_IN       16
#define F_EDGE     8
#define EMB        16
#define NUM_GRAPHS 256

// ---------------- scratch (no allocations allowed) ----------------
__device__ __align__(16) float g_sums[NUM_NODES * EMB];   // per-node message sums
__device__ float    g_cnt [NUM_NODES];                    // in-degree
__device__ float    g_gsum[NUM_GRAPHS * EMB];             // per-graph sum of h
__device__ unsigned g_gmax[NUM_GRAPHS * EMB];             // per-graph max of h (h>=0)
__device__ float    g_gcnt[NUM_GRAPHS];                   // nodes per graph
__device__ unsigned g_done;                               // node-block completion counter

// ---------------- packed f32x2 helpers (Blackwell) ----------------
__device__ __forceinline__ unsigned long long pk2(float lo, float hi) {
    unsigned long long r;
    asm("mov.b64 %0, {%1, %2};" : "=l"(r) : "f"(lo), "f"(hi));
    return r;
}
__device__ __forceinline__ void unpk2(unsigned long long v, float& lo, float& hi) {
    asm("mov.b64 {%0, %1}, %2;" : "=f"(lo), "=f"(hi) : "l"(v));
}
__device__ __forceinline__ unsigned long long fma2(unsigned long long a,
                                                   unsigned long long b,
                                                   unsigned long long c) {
    unsigned long long d;
    asm("fma.rn.f32x2 %0, %1, %2, %3;" : "=l"(d) : "l"(a), "l"(b), "l"(c));
    return d;
}

// ---------------- kernel 0: zero scratch ----------------
__global__ void zero_kernel() {
    int i = blockIdx.x * blockDim.x + threadIdx.x;
    int stride = gridDim.x * blockDim.x;
    float4 z4 = make_float4(0.f, 0.f, 0.f, 0.f);
    float4* s4 = reinterpret_cast<float4*>(g_sums);
    for (int k = i; k < NUM_NODES * EMB / 4; k += stride) s4[k] = z4;
    for (int k = i; k < NUM_NODES;       k += stride) g_cnt[k]  = 0.f;
    for (int k = i; k < NUM_GRAPHS * EMB; k += stride) { g_gsum[k] = 0.f; g_gmax[k] = 0u; }
    for (int k = i; k < NUM_GRAPHS;      k += stride) g_gcnt[k] = 0.f;
    if (i == 0) g_done = 0u;
}

// ---------------- kernel 1: per-edge MLP + message + scatter ----------------
// One warp per edge per iteration. lane = o + 16*half.
// Thread (o, half) owns MLP rows r = i*16+o for i in [half*8, half*8+8):
// 8 rows x 8 weights = 32 packed f32x2 regs. Halves combined via shfl_xor(16).
// 2-deep software pipeline hides the random x[src] gather latency.
#define EDGE_BLOCKS 592
__global__ __launch_bounds__(256, 2)
void edge_kernel(const float* __restrict__ x,
                 const int*   __restrict__ ei,
                 const float* __restrict__ ea,
                 const float* __restrict__ nn1_w,
                 const float* __restrict__ nn1_b) {
    const int lane = threadIdx.x & 31;
    const int o    = lane & 15;
    const int half = lane >> 4;
    const unsigned full = 0xffffffffu;

    // weight slice: 8 rows, packed over f
    unsigned long long w2[8][4];
    float b[8];
    #pragma unroll
    for (int k = 0; k < 8; k++) {
        const int r = (half * 8 + k) * 16 + o;
        const ulonglong2* p = reinterpret_cast<const ulonglong2*>(nn1_w + (size_t)r * 8);
        ulonglong2 a0 = p[0], a1 = p[1];
        w2[k][0] = a0.x; w2[k][1] = a0.y; w2[k][2] = a1.x; w2[k][3] = a1.y;
        b[k] = nn1_b[r];
    }

    const int warp = (blockIdx.x * blockDim.x + threadIdx.x) >> 5;
    const int step = (EDGE_BLOCKS * 256) >> 5;           // 4736 warps

    int e = warp;                                        // 4736 < NUM_EDGES always
    // ---- pipeline prologue ----
    int srcC = ei[e];
    int dstC = ei[NUM_EDGES + e];
    const ulonglong2* pc = reinterpret_cast<const ulonglong2*>(ea + (size_t)e * 8);
    ulonglong2 c0 = pc[0], c1 = pc[1];
    unsigned long long evC0 = c0.x, evC1 = c0.y, evC2 = c1.x, evC3 = c1.y;
    float xvC = x[(size_t)srcC * 16 + o];
    int e1 = (e + step < NUM_EDGES) ? e + step : NUM_EDGES - 1;
    int srcN = ei[e1];
    int dstN = ei[NUM_EDGES + e1];

    for (; e < NUM_EDGES; e += step) {
        // prefetch next edge's data (src known from last iteration)
        const int en = (e + step < NUM_EDGES) ? e + step : NUM_EDGES - 1;
        const ulonglong2* pn = reinterpret_cast<const ulonglong2*>(ea + (size_t)en * 8);
        ulonglong2 n0 = pn[0], n1 = pn[1];
        const float xvN = x[(size_t)srcN * 16 + o];
        // prefetch next-next indices
        const int enn = (e + 2 * step < NUM_EDGES) ? e + 2 * step : NUM_EDGES - 1;
        const int srcNN = ei[enn];
        const int dstNN = ei[NUM_EDGES + enn];

        // ---- compute current edge ----
        float acc = 0.f;
        #pragma unroll
        for (int k = 0; k < 8; k++) {
            unsigned long long t2 = fma2(evC0, w2[k][0], pk2(b[k], 0.f));
            t2 = fma2(evC1, w2[k][1], t2);
            t2 = fma2(evC2, w2[k][2], t2);
            t2 = fma2(evC3, w2[k][3], t2);
            float lo, hi; unpk2(t2, lo, hi);
            const float t = fmaxf(lo + hi, 0.f);               // relu(hidden[i,o])
            const float xi = __shfl_sync(full, xvC, half * 8 + k);
            acc = fmaf(xi, t, acc);
        }
        acc += __shfl_xor_sync(full, acc, 16);                 // combine halves
        if (half == 0) atomicAdd(&g_sums[(size_t)dstC * 16 + o], acc);
        if (lane == 0) atomicAdd(&g_cnt[dstC], 1.f);

        // ---- shift pipeline ----
        evC0 = n0.x; evC1 = n0.y; evC2 = n1.x; evC3 = n1.y;
        xvC = xvN; dstC = dstN;
        srcN = srcNN; dstN = dstNN;
    }
}

// ---------------- kernel 2: node update + pooling + fused head ----------------
__global__ __launch_bounds__(256)
void node_kernel(const float* __restrict__ x,
                 const int*   __restrict__ batch,
                 const float* __restrict__ root_w,
                 const float* __restrict__ conv_b,
                 const float* __restrict__ lin1_w,
                 const float* __restrict__ lin1_b,
                 const float* __restrict__ lin2_w,
                 const float* __restrict__ lin2_b,
                 float* __restrict__ out) {
    __shared__ float rw[256];
    __shared__ float cb[16];
    __shared__ unsigned sLast;
    rw[threadIdx.x] = root_w[threadIdx.x];
    if (threadIdx.x < 16) cb[threadIdx.x] = conv_b[threadIdx.x];
    __syncthreads();

    const int n = blockIdx.x * blockDim.x + threadIdx.x;
    const unsigned full = 0xffffffffu;
    const int lane = threadIdx.x & 31;

    if (n < NUM_NODES) {   // NUM_NODES % 32 == 0 -> whole warps in/out together
        float xr[16];
        {
            const float4* px = reinterpret_cast<const float4*>(x + (size_t)n * 16);
            float4 a = px[0], bq = px[1], c = px[2], d = px[3];
            xr[0]=a.x; xr[1]=a.y; xr[2]=a.z; xr[3]=a.w;
            xr[4]=bq.x; xr[5]=bq.y; xr[6]=bq.z; xr[7]=bq.w;
            xr[8]=c.x; xr[9]=c.y; xr[10]=c.z; xr[11]=c.w;
            xr[12]=d.x; xr[13]=d.y; xr[14]=d.z; xr[15]=d.w;
        }
        float s[16];
        {
            const float4* ps = reinterpret_cast<const float4*>(g_sums + (size_t)n * 16);
            float4 a = ps[0], bq = ps[1], c = ps[2], d = ps[3];
            s[0]=a.x; s[1]=a.y; s[2]=a.z; s[3]=a.w;
            s[4]=bq.x; s[5]=bq.y; s[6]=bq.z; s[7]=bq.w;
            s[8]=c.x; s[9]=c.y; s[10]=c.z; s[11]=c.w;
            s[12]=d.x; s[13]=d.y; s[14]=d.z; s[15]=d.w;
        }
        const float inv = 1.f / fmaxf(g_cnt[n], 1.f);

        float h[16];
        #pragma unroll
        for (int o = 0; o < 16; o++) {
            float a = fmaf(s[o], inv, cb[o]);
            #pragma unroll
            for (int i = 0; i < 16; i++) a = fmaf(xr[i], rw[o * 16 + i], a);
            h[o] = fmaxf(a, 0.f);
        }

        const int g = batch[n];
        const int g0 = __shfl_sync(full, g, 0);
        const bool uni = __all_sync(full, g == g0);

        if (uni) {
            #pragma unroll
            for (int o = 0; o < 16; o++) {
                float sv = h[o], mv = h[o];
                #pragma unroll
                for (int off = 16; off > 0; off >>= 1) {
                    sv += __shfl_xor_sync(full, sv, off);
                    mv = fmaxf(mv, __shfl_xor_sync(full, mv, off));
                }
                if (lane == 0) {
                    atomicAdd(&g_gsum[g0 * 16 + o], sv);
                    atomicMax(&g_gmax[g0 * 16 + o], __float_as_uint(mv));
                }
            }
            if (lane == 0) atomicAdd(&g_gcnt[g0], 32.f);
        } else {
            #pragma unroll
            for (int o = 0; o < 16; o++) {
                atomicAdd(&g_gsum[g * 16 + o], h[o]);
                atomicMax(&g_gmax[g * 16 + o], __float_as_uint(h[o]));
            }
            atomicAdd(&g_gcnt[g], 1.f);
        }
    }

    // ---- fused head: last block to finish computes the per-graph MLP ----
    __threadfence();
    __syncthreads();
    if (threadIdx.x == 0)
        sLast = (atomicInc(&g_done, 0xffffffffu) == gridDim.x - 1) ? 1u : 0u;
    __syncthreads();
    if (!sLast) return;

    __shared__ float w1[16 * 32];
    __shared__ float b1[16];
    __shared__ float w2h[16];
    __shared__ float b2;
    for (int i = threadIdx.x; i < 16 * 32; i += blockDim.x) w1[i] = lin1_w[i];
    if (threadIdx.x < 16) { b1[threadIdx.x] = lin1_b[threadIdx.x]; w2h[threadIdx.x] = lin2_w[threadIdx.x]; }
    if (threadIdx.x == 0) b2 = lin2_b[0];
    __syncthreads();

    const int g = threadIdx.x;   // 256 graphs, 256 threads
    float p[32];
    #pragma unroll
    for (int j = 0; j < 16; j++) p[j] = __uint_as_float(__ldcg(&g_gmax[g * 16 + j]));
    const float inv = 1.f / fmaxf(__ldcg(&g_gcnt[g]), 1.f);
    #pragma unroll
    for (int j = 0; j < 16; j++) p[16 + j] = __ldcg(&g_gsum[g * 16 + j]) * inv;

    float acc = b2;
    #pragma unroll
    for (int k = 0; k < 16; k++) {
        float a = b1[k];
        #pragma unroll
        for (int j = 0; j < 32; j++) a = fmaf(p[j], w1[k * 32 + j], a);
        acc = fmaf(fmaxf(a, 0.f), w2h[k], acc);
    }
    out[g] = acc;
}

// ---------------- launch ----------------
extern "C" void kernel_launch(void* const* d_in, const int* in_sizes, int n_in,
                              void* d_out, int out_size) {
    const float* x      = (const float*)d_in[0];
    const int*   ei     = (const int*)  d_in[1];
    const float* ea     = (const float*)d_in[2];
    const int*   batch  = (const int*)  d_in[3];
    const float* nn1_w  = (const float*)d_in[4];
    const float* nn1_b  = (const float*)d_in[5];
    const float* root_w = (const float*)d_in[6];
    const float* conv_b = (const float*)d_in[7];
    const float* lin1_w = (const float*)d_in[8];
    const float* lin1_b = (const float*)d_in[9];
    const float* lin2_w = (const float*)d_in[10];
    const float* lin2_b = (const float*)d_in[11];
    float* out = (float*)d_out;

    zero_kernel<<<512, 256>>>();
    edge_kernel<<<EDGE_BLOCKS, 256>>>(x, ei, ea, nn1_w, nn1_b);
    node_kernel<<<(NUM_NODES + 255) / 256, 256>>>(x, batch, root_w, conv_b,
                                                  lin1_w, lin1_b, lin2_w, lin2_b, out);
}

// round 12
// speedup vs baseline: 1.5646x; 1.0830x over previous
#include <cuda_runtime.h>
#include <cstdint>

#define NUM_NODES  100000
#define NUM_EDGES  400000
#define F_IN       16
#define F_EDGE     8
#define EMB        16
#define NUM_GRAPHS 256

// ---------------- scratch (no allocations allowed) ----------------
__device__ __align__(16) float g_sums[NUM_NODES * EMB];   // per-node message sums
__device__ float    g_cnt [NUM_NODES];                    // in-degree
__device__ float    g_gsum[NUM_GRAPHS * EMB];             // per-graph sum of h
__device__ unsigned g_gmax[NUM_GRAPHS * EMB];             // per-graph max of h (h>=0)
__device__ float    g_gcnt[NUM_GRAPHS];                   // nodes per graph
__device__ unsigned g_done;                               // node-block completion counter

// ---------------- packed f32x2 helpers (Blackwell) ----------------
__device__ __forceinline__ unsigned long long pk2(float lo, float hi) {
    unsigned long long r;
    asm("mov.b64 %0, {%1, %2};" : "=l"(r) : "f"(lo), "f"(hi));
    return r;
}
__device__ __forceinline__ void unpk2(unsigned long long v, float& lo, float& hi) {
    asm("mov.b64 {%0, %1}, %2;" : "=f"(lo), "=f"(hi) : "l"(v));
}
__device__ __forceinline__ unsigned long long fma2(unsigned long long a,
                                                   unsigned long long b,
                                                   unsigned long long c) {
    unsigned long long d;
    asm("fma.rn.f32x2 %0, %1, %2, %3;" : "=l"(d) : "l"(a), "l"(b), "l"(c));
    return d;
}

// ---------------- kernel 0: zero scratch ----------------
__global__ void zero_kernel() {
    int i = blockIdx.x * blockDim.x + threadIdx.x;
    int stride = gridDim.x * blockDim.x;
    float4 z4 = make_float4(0.f, 0.f, 0.f, 0.f);
    float4* s4 = reinterpret_cast<float4*>(g_sums);
    for (int k = i; k < NUM_NODES * EMB / 4; k += stride) s4[k] = z4;
    for (int k = i; k < NUM_NODES;       k += stride) g_cnt[k]  = 0.f;
    for (int k = i; k < NUM_GRAPHS * EMB; k += stride) { g_gsum[k] = 0.f; g_gmax[k] = 0u; }
    for (int k = i; k < NUM_GRAPHS;      k += stride) g_gcnt[k] = 0.f;
    if (i == 0) g_done = 0u;
}

// ---------------- kernel 1: per-edge MLP + message + scatter ----------------
// One warp per edge per iteration. lane = o + 16*half.
// Thread (o, half) owns MLP rows r = i*16+o for i in [half*8, half*8+8).
// x values needed are x[src*16 + half*8 .. +8): loaded directly as 2x float4
// (2 distinct addresses/warp -> broadcast) -> NO per-row shuffles.
// One shfl_xor(16) combines halves. 2-stage pipeline + unroll 2 (rename shifts).
#define EDGE_BLOCKS 296
#define EDGE_WARPS  (EDGE_BLOCKS * 8)   // 2368 warps = exactly one wave @ 2 CTAs/SM
__global__ __launch_bounds__(256, 2)
void edge_kernel(const float* __restrict__ x,
                 const int*   __restrict__ ei,
                 const float* __restrict__ ea,
                 const float* __restrict__ nn1_w,
                 const float* __restrict__ nn1_b) {
    const int lane = threadIdx.x & 31;
    const int o    = lane & 15;
    const int half = lane >> 4;
    const unsigned full = 0xffffffffu;

    // weight slice: 8 rows (i = half*8+k), packed over f
    unsigned long long w2[8][4];
    float b[8];
    #pragma unroll
    for (int k = 0; k < 8; k++) {
        const int r = (half * 8 + k) * 16 + o;
        const ulonglong2* p = reinterpret_cast<const ulonglong2*>(nn1_w + (size_t)r * 8);
        ulonglong2 a0 = p[0], a1 = p[1];
        w2[k][0] = a0.x; w2[k][1] = a0.y; w2[k][2] = a1.x; w2[k][3] = a1.y;
        b[k] = nn1_b[r];
    }

    const int warp = (blockIdx.x * blockDim.x + threadIdx.x) >> 5;
    const int step = EDGE_WARPS;
    const int xoff = half * 8;

    int e = warp;
    // ---- pipeline prologue ----
    int srcC = ei[e];
    int dstC = ei[NUM_EDGES + e];
    float4 xa = *reinterpret_cast<const float4*>(x + (size_t)srcC * 16 + xoff);
    float4 xb = *reinterpret_cast<const float4*>(x + (size_t)srcC * 16 + xoff + 4);
    ulonglong2 ea0 = reinterpret_cast<const ulonglong2*>(ea + (size_t)e * 8)[0];
    ulonglong2 ea1 = reinterpret_cast<const ulonglong2*>(ea + (size_t)e * 8)[1];
    int e1 = (e + step < NUM_EDGES) ? e + step : NUM_EDGES - 1;
    int srcN = ei[e1];
    int dstN = ei[NUM_EDGES + e1];

    #pragma unroll 2
    for (; e < NUM_EDGES; e += step) {
        // prefetch next edge's data (src known from previous iteration)
        const int en = (e + step < NUM_EDGES) ? e + step : NUM_EDGES - 1;
        const float4 xna = *reinterpret_cast<const float4*>(x + (size_t)srcN * 16 + xoff);
        const float4 xnb = *reinterpret_cast<const float4*>(x + (size_t)srcN * 16 + xoff + 4);
        const ulonglong2 ean0 = reinterpret_cast<const ulonglong2*>(ea + (size_t)en * 8)[0];
        const ulonglong2 ean1 = reinterpret_cast<const ulonglong2*>(ea + (size_t)en * 8)[1];
        // prefetch next-next indices
        const int enn = (e + 2 * step < NUM_EDGES) ? e + 2 * step : NUM_EDGES - 1;
        const int srcNN = ei[enn];
        const int dstNN = ei[NUM_EDGES + enn];

        // ---- compute current edge ----
        const float xr[8] = {xa.x, xa.y, xa.z, xa.w, xb.x, xb.y, xb.z, xb.w};
        float acc = 0.f;
        #pragma unroll
        for (int k = 0; k < 8; k++) {
            unsigned long long t2 = fma2(ea0.x, w2[k][0], pk2(b[k], 0.f));
            t2 = fma2(ea0.y, w2[k][1], t2);
            t2 = fma2(ea1.x, w2[k][2], t2);
            t2 = fma2(ea1.y, w2[k][3], t2);
            float lo, hi; unpk2(t2, lo, hi);
            const float t = fmaxf(lo + hi, 0.f);               // relu(hidden[i,o])
            acc = fmaf(xr[k], t, acc);
        }
        acc += __shfl_xor_sync(full, acc, 16);                 // combine halves
        if (half == 0) atomicAdd(&g_sums[(size_t)dstC * 16 + o], acc);
        if (lane == 0) atomicAdd(&g_cnt[dstC], 1.f);

        // ---- shift pipeline (renamed away by unroll 2) ----
        xa = xna; xb = xnb; ea0 = ean0; ea1 = ean1;
        dstC = dstN; srcN = srcNN; dstN = dstNN;
    }
}

// ---------------- kernel 2: node update + pooling + fused head ----------------
__global__ __launch_bounds__(256)
void node_kernel(const float* __restrict__ x,
                 const int*   __restrict__ batch,
                 const float* __restrict__ root_w,
                 const float* __restrict__ conv_b,
                 const float* __restrict__ lin1_w,
                 const float* __restrict__ lin1_b,
                 const float* __restrict__ lin2_w,
                 const float* __restrict__ lin2_b,
                 float* __restrict__ out) {
    __shared__ float rw[256];
    __shared__ float cb[16];
    __shared__ unsigned sLast;
    rw[threadIdx.x] = root_w[threadIdx.x];
    if (threadIdx.x < 16) cb[threadIdx.x] = conv_b[threadIdx.x];
    __syncthreads();

    const int n = blockIdx.x * blockDim.x + threadIdx.x;
    const unsigned full = 0xffffffffu;
    const int lane = threadIdx.x & 31;

    if (n < NUM_NODES) {   // NUM_NODES % 32 == 0 -> whole warps in/out together
        float xr[16];
        {
            const float4* px = reinterpret_cast<const float4*>(x + (size_t)n * 16);
            float4 a = px[0], bq = px[1], c = px[2], d = px[3];
            xr[0]=a.x; xr[1]=a.y; xr[2]=a.z; xr[3]=a.w;
            xr[4]=bq.x; xr[5]=bq.y; xr[6]=bq.z; xr[7]=bq.w;
            xr[8]=c.x; xr[9]=c.y; xr[10]=c.z; xr[11]=c.w;
            xr[12]=d.x; xr[13]=d.y; xr[14]=d.z; xr[15]=d.w;
        }
        float s[16];
        {
            const float4* ps = reinterpret_cast<const float4*>(g_sums + (size_t)n * 16);
            float4 a = ps[0], bq = ps[1], c = ps[2], d = ps[3];
            s[0]=a.x; s[1]=a.y; s[2]=a.z; s[3]=a.w;
            s[4]=bq.x; s[5]=bq.y; s[6]=bq.z; s[7]=bq.w;
            s[8]=c.x; s[9]=c.y; s[10]=c.z; s[11]=c.w;
            s[12]=d.x; s[13]=d.y; s[14]=d.z; s[15]=d.w;
        }
        const float inv = 1.f / fmaxf(g_cnt[n], 1.f);

        float h[16];
        #pragma unroll
        for (int o = 0; o < 16; o++) {
            float a = fmaf(s[o], inv, cb[o]);
            #pragma unroll
            for (int i = 0; i < 16; i++) a = fmaf(xr[i], rw[o * 16 + i], a);
            h[o] = fmaxf(a, 0.f);
        }

        const int g = batch[n];
        const int g0 = __shfl_sync(full, g, 0);
        const bool uni = __all_sync(full, g == g0);

        if (uni) {
            #pragma unroll
            for (int o = 0; o < 16; o++) {
                float sv = h[o], mv = h[o];
                #pragma unroll
                for (int off = 16; off > 0; off >>= 1) {
                    sv += __shfl_xor_sync(full, sv, off);
                    mv = fmaxf(mv, __shfl_xor_sync(full, mv, off));
                }
                if (lane == 0) {
                    atomicAdd(&g_gsum[g0 * 16 + o], sv);
                    atomicMax(&g_gmax[g0 * 16 + o], __float_as_uint(mv));
                }
            }
            if (lane == 0) atomicAdd(&g_gcnt[g0], 32.f);
        } else {
            #pragma unroll
            for (int o = 0; o < 16; o++) {
                atomicAdd(&g_gsum[g * 16 + o], h[o]);
                atomicMax(&g_gmax[g * 16 + o], __float_as_uint(h[o]));
            }
            atomicAdd(&g_gcnt[g], 1.f);
        }
    }

    // ---- fused head: last block to finish computes the per-graph MLP ----
    __threadfence();
    __syncthreads();
    if (threadIdx.x == 0)
        sLast = (atomicInc(&g_done, 0xffffffffu) == gridDim.x - 1) ? 1u : 0u;
    __syncthreads();
    if (!sLast) return;

    __shared__ float w1[16 * 32];
    __shared__ float b1[16];
    __shared__ float w2h[16];
    __shared__ float b2;
    for (int i = threadIdx.x; i < 16 * 32; i += blockDim.x) w1[i] = lin1_w[i];
    if (threadIdx.x < 16) { b1[threadIdx.x] = lin1_b[threadIdx.x]; w2h[threadIdx.x] = lin2_w[threadIdx.x]; }
    if (threadIdx.x == 0) b2 = lin2_b[0];
    __syncthreads();

    const int g = threadIdx.x;   // 256 graphs, 256 threads
    float p[32];
    #pragma unroll
    for (int j = 0; j < 16; j++) p[j] = __uint_as_float(__ldcg(&g_gmax[g * 16 + j]));
    const float inv = 1.f / fmaxf(__ldcg(&g_gcnt[g]), 1.f);
    #pragma unroll
    for (int j = 0; j < 16; j++) p[16 + j] = __ldcg(&g_gsum[g * 16 + j]) * inv;

    float acc = b2;
    #pragma unroll
    for (int k = 0; k < 16; k++) {
        float a = b1[k];
        #pragma unroll
        for (int j = 0; j < 32; j++) a = fmaf(p[j], w1[k * 32 + j], a);
        acc = fmaf(fmaxf(a, 0.f), w2h[k], acc);
    }
    out[g] = acc;
}

// ---------------- launch ----------------
extern "C" void kernel_launch(void* const* d_in, const int* in_sizes, int n_in,
                              void* d_out, int out_size) {
    const float* x      = (const float*)d_in[0];
    const int*   ei     = (const int*)  d_in[1];
    const float* ea     = (const float*)d_in[2];
    const int*   batch  = (const int*)  d_in[3];
    const float* nn1_w  = (const float*)d_in[4];
    const float* nn1_b  = (const float*)d_in[5];
    const float* root_w = (const float*)d_in[6];
    const float* conv_b = (const float*)d_in[7];
    const float* lin1_w = (const float*)d_in[8];
    const float* lin1_b = (const float*)d_in[9];
    const float* lin2_w = (const float*)d_in[10];
    const float* lin2_b = (const float*)d_in[11];
    float* out = (float*)d_out;

    zero_kernel<<<512, 256>>>();
    edge_kernel<<<EDGE_BLOCKS, 256>>>(x, ei, ea, nn1_w, nn1_b);
    node_kernel<<<(NUM_NODES + 255) / 256, 256>>>(x, batch, root_w, conv_b,
                                                  lin1_w, lin1_b, lin2_w, lin2_b, out);
}